// round 9
// baseline (speedup 1.0000x reference)
#include <cuda_runtime.h>
#include <cuda_fp16.h>
#include <cstdint>

#define D 128
#define NMAX 100000
#define EMAX 3200000
#define FULL 0xffffffffu

// Scratch in device globals (no runtime allocation).
__device__ float  g_h0[NMAX * D];
__device__ __half g_h1h[NMAX * D];      // h1 in fp16 (agg gather payload)
__device__ float  g_aself[NMAX];
__device__ float  g_aneigh[NMAX];
__device__ int    g_deg[NMAX + 4];      // padded for int4 scan reads
__device__ int    g_off[NMAX + 1];
__device__ int    g_cur[NMAX];
__device__ int2   g_epack[EMAX];        // {col, f32 bits of a_neigh[col]}

// ---------------------------------------------------------------------------
// Tensor-core GEMM (tf32 mma.sync m16n8k8).
// Grid (ceil(N/128), 2): cb=0 -> h0 (fp32) + a_self; cb=1 -> h1 (fp16) + a_neigh.
// ---------------------------------------------------------------------------
#define TSTRIDE 132
#define TILE_WORDS (128 * TSTRIDE)
#define GEMM_SMEM ((2 * TILE_WORDS + 3 * 128) * 4)

__device__ __forceinline__ uint32_t f2tf32(float f)
{
    uint32_t u;
    asm("cvt.rna.tf32.f32 %0, %1;" : "=r"(u) : "f"(f));
    return u;
}

__device__ __forceinline__ void mma_tf32(float* c, const uint32_t* a,
                                         uint32_t b0, uint32_t b1)
{
    asm volatile(
        "mma.sync.aligned.m16n8k8.row.col.f32.tf32.tf32.f32 "
        "{%0,%1,%2,%3}, {%4,%5,%6,%7}, {%8,%9}, {%0,%1,%2,%3};"
        : "+f"(c[0]), "+f"(c[1]), "+f"(c[2]), "+f"(c[3])
        : "r"(a[0]), "r"(a[1]), "r"(a[2]), "r"(a[3]), "r"(b0), "r"(b1));
}

__global__ __launch_bounds__(256) void gemm_kernel(
    const float* __restrict__ x,
    const float* __restrict__ W0, const float* __restrict__ b0,
    const float* __restrict__ W1, const float* __restrict__ b1,
    const float* __restrict__ att, int N)
{
    extern __shared__ uint32_t sm[];
    uint32_t* xs = sm;
    uint32_t* ws = sm + TILE_WORDS;
    float* rowsum = (float*)(sm + 2 * TILE_WORDS);
    float* sbias  = rowsum + 128;
    float* satt   = sbias + 128;

    const int tid  = threadIdx.x;
    const int row0 = blockIdx.x * 128;
    const int cb   = blockIdx.y;
    const float* W  = cb ? W1 : W0;
    const float* bv = cb ? b1 : b0;

    if (tid < 128) {
        rowsum[tid] = 0.0f;
        sbias[tid]  = bv[tid];
        satt[tid]   = att[cb * 128 + tid];
    }

    for (int i = tid; i < 128 * 128; i += 256) {
        int r = i >> 7, c = i & 127;
        int gr = row0 + r;
        float xv = (gr < N) ? x[(size_t)gr * 128 + c] : 0.0f;
        xs[r * TSTRIDE + c] = f2tf32(xv);
        ws[r * TSTRIDE + c] = f2tf32(W[r * 128 + c]);
    }
    __syncthreads();

    const int lane = tid & 31, wid = tid >> 5;
    const int gid  = lane >> 2, tg = lane & 3;
    const int mrow = (wid >> 1) * 32;
    const int ncol = (wid & 1) * 64;

    float acc[2][8][4];
#pragma unroll
    for (int mt = 0; mt < 2; mt++)
#pragma unroll
        for (int nt = 0; nt < 8; nt++)
#pragma unroll
            for (int q = 0; q < 4; q++) acc[mt][nt][q] = 0.0f;

#pragma unroll 2
    for (int ks = 0; ks < 16; ks++) {
        const int k0 = ks * 8;
        uint32_t a[2][4];
#pragma unroll
        for (int mt = 0; mt < 2; mt++) {
            int r = mrow + mt * 16 + gid;
            a[mt][0] = xs[(r    ) * TSTRIDE + k0 + tg    ];
            a[mt][1] = xs[(r + 8) * TSTRIDE + k0 + tg    ];
            a[mt][2] = xs[(r    ) * TSTRIDE + k0 + tg + 4];
            a[mt][3] = xs[(r + 8) * TSTRIDE + k0 + tg + 4];
        }
#pragma unroll
        for (int nt = 0; nt < 8; nt++) {
            int n = ncol + nt * 8 + gid;
            uint32_t bq0 = ws[n * TSTRIDE + k0 + tg    ];
            uint32_t bq1 = ws[n * TSTRIDE + k0 + tg + 4];
#pragma unroll
            for (int mt = 0; mt < 2; mt++)
                mma_tf32(acc[mt][nt], a[mt], bq0, bq1);
        }
    }

    float pr[2][2] = {{0.f, 0.f}, {0.f, 0.f}};
#pragma unroll
    for (int mt = 0; mt < 2; mt++) {
        int rbase = row0 + mrow + mt * 16;
#pragma unroll
        for (int nt = 0; nt < 8; nt++) {
            int n = ncol + nt * 8 + 2 * tg;
            float bia0 = sbias[n], bia1 = sbias[n + 1];
            float at0  = satt[n],  at1  = satt[n + 1];
            float v00 = fmaxf(acc[mt][nt][0] + bia0, 0.0f);
            float v01 = fmaxf(acc[mt][nt][1] + bia1, 0.0f);
            float v10 = fmaxf(acc[mt][nt][2] + bia0, 0.0f);
            float v11 = fmaxf(acc[mt][nt][3] + bia1, 0.0f);
            int r0r = rbase + gid, r1r = rbase + gid + 8;
            if (cb == 0) {
                if (r0r < N) *(float2*)(g_h0 + (size_t)r0r * 128 + n) = make_float2(v00, v01);
                if (r1r < N) *(float2*)(g_h0 + (size_t)r1r * 128 + n) = make_float2(v10, v11);
            } else {
                if (r0r < N) *(__half2*)(g_h1h + (size_t)r0r * 128 + n) =
                    __floats2half2_rn(v00, v01);
                if (r1r < N) *(__half2*)(g_h1h + (size_t)r1r * 128 + n) =
                    __floats2half2_rn(v10, v11);
            }
            pr[mt][0] += v00 * at0 + v01 * at1;
            pr[mt][1] += v10 * at0 + v11 * at1;
        }
    }
#pragma unroll
    for (int mt = 0; mt < 2; mt++)
#pragma unroll
        for (int h = 0; h < 2; h++) {
            float p = pr[mt][h];
            p += __shfl_xor_sync(FULL, p, 1);
            p += __shfl_xor_sync(FULL, p, 2);
            pr[mt][h] = p;
        }
    if (tg == 0) {
        atomicAdd(&rowsum[mrow + gid     ], pr[0][0]);
        atomicAdd(&rowsum[mrow + gid + 8 ], pr[0][1]);
        atomicAdd(&rowsum[mrow + gid + 16], pr[1][0]);
        atomicAdd(&rowsum[mrow + gid + 24], pr[1][1]);
    }
    __syncthreads();
    if (tid < 128) {
        int gr = row0 + tid;
        if (gr < N) {
            float p = rowsum[tid];
            p = (p > 0.0f) ? p : 0.2f * p;
            if (cb) g_aneigh[gr] = p;
            else    g_aself[gr]  = p;
        }
    }
}

// ---------------------------------------------------------------------------
// Side-stream chain: zero_deg -> hist -> scan (single block) ; overlapped
// with the GEMM on stream 0.
// ---------------------------------------------------------------------------
__global__ __launch_bounds__(256) void zero_deg_kernel(int N)
{
    int i = blockIdx.x * 256 + threadIdx.x;
    if (i < N + 4) g_deg[i] = 0;
}

__global__ __launch_bounds__(256) void hist_kernel(const int* __restrict__ row, int E)
{
    int i = blockIdx.x * 256 + threadIdx.x;
    if (i < E) atomicAdd(&g_deg[row[i]], 1);
}

// Single-block exclusive scan of g_deg[0..N) -> g_off (inclusive at i+1),
// g_cur[i] = exclusive prefix. 1024 threads, 100-element chunks (int4 loads).
#define SCAN_CHUNK 100
__global__ __launch_bounds__(1024) void scan_kernel(int N)
{
    __shared__ int wsum[32];
    const int t = threadIdx.x;
    const int base = t * SCAN_CHUNK;

    // Pass 1: chunk sum.
    int sum = 0;
#pragma unroll
    for (int u = 0; u < SCAN_CHUNK / 4; u++) {
        int idx = base + u * 4;
        if (idx < N) {
            int4 v = *(const int4*)(g_deg + idx);   // g_deg padded by 4
            sum += v.x;
            if (idx + 1 < N) sum += v.y;
            if (idx + 2 < N) sum += v.z;
            if (idx + 3 < N) sum += v.w;
        }
    }

    // Block-wide exclusive scan of the 1024 chunk sums.
    const int lane = t & 31, w = t >> 5;
    int v = sum;
#pragma unroll
    for (int o = 1; o < 32; o <<= 1) {
        int n = __shfl_up_sync(FULL, v, o);
        if (lane >= o) v += n;
    }
    if (lane == 31) wsum[w] = v;
    __syncthreads();
    if (w == 0) {
        int s = wsum[lane];
#pragma unroll
        for (int o = 1; o < 32; o <<= 1) {
            int n = __shfl_up_sync(FULL, s, o);
            if (lane >= o) s += n;
        }
        wsum[lane] = s;
    }
    __syncthreads();
    int excl = v - sum + (w > 0 ? wsum[w - 1] : 0);

    // Pass 2: write prefix (g_cur) and inclusive (g_off[i+1]).
    int running = excl;
#pragma unroll
    for (int u = 0; u < SCAN_CHUNK / 4; u++) {
        int idx = base + u * 4;
        if (idx < N) {
            int4 dv = *(const int4*)(g_deg + idx);
            int d[4] = {dv.x, dv.y, dv.z, dv.w};
#pragma unroll
            for (int q = 0; q < 4; q++) {
                if (idx + q < N) {
                    g_cur[idx + q] = running;
                    running += d[q];
                    g_off[idx + q + 1] = running;
                }
            }
        }
    }
    if (t == 0) g_off[0] = 0;
}

__global__ __launch_bounds__(256) void scatter_kernel(
    const int* __restrict__ row, const int* __restrict__ col, int E)
{
    int i = blockIdx.x * 256 + threadIdx.x;
    if (i < E) {
        int c = col[i];
        int pos = atomicAdd(&g_cur[row[i]], 1);
        g_epack[pos] = make_int2(c, __float_as_int(g_aneigh[c]));
    }
}

// ---------------------------------------------------------------------------
// Aggregate + fused epilogue: one warp per node (gather, no atomics).
//   agg = sum_{(r,c)} (a_self[r]+a_neigh[c]) * h1[c]   (h1 fp16, e pre-packed)
//   out[r] = norm(h0[r],s0,o0) + norm(agg,s1,o1)
// ---------------------------------------------------------------------------
__global__ __launch_bounds__(256) void agg_kernel(
    const float* __restrict__ scale0, const float* __restrict__ offset0,
    const float* __restrict__ scale1, const float* __restrict__ offset1,
    float* __restrict__ out, int N)
{
    int gw = (blockIdx.x * blockDim.x + threadIdx.x) >> 5;
    int lane = threadIdx.x & 31;
    if (gw >= N) return;

    const int start = g_off[gw];
    const int end   = g_off[gw + 1];
    const float a_r = g_aself[gw];

    float4 acc = make_float4(0.f, 0.f, 0.f, 0.f);

    for (int base = start; base < end; base += 32) {
        int idx = base + lane;
        int2 p = (idx < end) ? g_epack[idx] : make_int2(0, 0);
        int   c = p.x;
        float e = a_r + __int_as_float(p.y);
        int cnt = min(32, end - base);
        int j = 0;
        for (; j + 4 <= cnt; j += 4) {
#pragma unroll
            for (int u = 0; u < 4; u++) {
                int   cj = __shfl_sync(FULL, c, j + u);
                float ej = __shfl_sync(FULL, e, j + u);
                uint2 hp = ((const uint2*)(g_h1h + (size_t)cj * 128))[lane];
                float2 lo = __half22float2(*(__half2*)&hp.x);
                float2 hi = __half22float2(*(__half2*)&hp.y);
                acc.x = fmaf(ej, lo.x, acc.x);
                acc.y = fmaf(ej, lo.y, acc.y);
                acc.z = fmaf(ej, hi.x, acc.z);
                acc.w = fmaf(ej, hi.y, acc.w);
            }
        }
        for (; j < cnt; j++) {
            int   cj = __shfl_sync(FULL, c, j);
            float ej = __shfl_sync(FULL, e, j);
            uint2 hp = ((const uint2*)(g_h1h + (size_t)cj * 128))[lane];
            float2 lo = __half22float2(*(__half2*)&hp.x);
            float2 hi = __half22float2(*(__half2*)&hp.y);
            acc.x = fmaf(ej, lo.x, acc.x);
            acc.y = fmaf(ej, lo.y, acc.y);
            acc.z = fmaf(ej, hi.x, acc.z);
            acc.w = fmaf(ej, hi.y, acc.w);
        }
    }

    const float4 h0v = ((const float4*)(g_h0 + (size_t)gw * 128))[lane];

    float s0 = h0v.x + h0v.y + h0v.z + h0v.w;
    float q0 = h0v.x * h0v.x + h0v.y * h0v.y + h0v.z * h0v.z + h0v.w * h0v.w;
    float s1 = acc.x + acc.y + acc.z + acc.w;
    float q1 = acc.x * acc.x + acc.y * acc.y + acc.z * acc.z + acc.w * acc.w;

#pragma unroll
    for (int o = 16; o > 0; o >>= 1) {
        s0 += __shfl_xor_sync(FULL, s0, o);
        q0 += __shfl_xor_sync(FULL, q0, o);
        s1 += __shfl_xor_sync(FULL, s1, o);
        q1 += __shfl_xor_sync(FULL, q1, o);
    }

    const float m0 = s0 * (1.0f / 128.0f);
    const float i0 = rsqrtf(q0 * (1.0f / 128.0f) - m0 * m0 + 1e-9f);
    const float m1 = s1 * (1.0f / 128.0f);
    const float i1 = rsqrtf(q1 * (1.0f / 128.0f) - m1 * m1 + 1e-9f);

    const float4 sc0 = ((const float4*)scale0)[lane];
    const float4 of0 = ((const float4*)offset0)[lane];
    const float4 sc1 = ((const float4*)scale1)[lane];
    const float4 of1 = ((const float4*)offset1)[lane];

    float4 o4;
    o4.x = (h0v.x - m0) * sc0.x * i0 + of0.x + (acc.x - m1) * sc1.x * i1 + of1.x;
    o4.y = (h0v.y - m0) * sc0.y * i0 + of0.y + (acc.y - m1) * sc1.y * i1 + of1.y;
    o4.z = (h0v.z - m0) * sc0.z * i0 + of0.z + (acc.z - m1) * sc1.z * i1 + of1.z;
    o4.w = (h0v.w - m0) * sc0.w * i0 + of0.w + (acc.w - m1) * sc1.w * i1 + of1.w;
    ((float4*)(out + (size_t)gw * 128))[lane] = o4;
}

// ---------------------------------------------------------------------------
extern "C" void kernel_launch(void* const* d_in, const int* in_sizes, int n_in,
                              void* d_out, int out_size)
{
    const float* x       = (const float*)d_in[0];
    const int*   row     = (const int*)  d_in[1];
    const int*   col     = (const int*)  d_in[2];
    const float* W0      = (const float*)d_in[3];
    const float* b0      = (const float*)d_in[4];
    const float* W1      = (const float*)d_in[5];
    const float* b1      = (const float*)d_in[6];
    const float* att     = (const float*)d_in[7];
    const float* scale0  = (const float*)d_in[8];
    const float* offset0 = (const float*)d_in[9];
    const float* scale1  = (const float*)d_in[10];
    const float* offset1 = (const float*)d_in[11];
    float* out = (float*)d_out;

    const int N = in_sizes[0] / D;
    const int E = in_sizes[1];

    // One-time host-side resources (created on the uncaptured correctness call).
    static cudaStream_t s_side = nullptr;
    static cudaEvent_t  s_evFork = nullptr, s_evJoin = nullptr;
    if (!s_side) {
        cudaStreamCreateWithFlags(&s_side, cudaStreamNonBlocking);
        cudaEventCreateWithFlags(&s_evFork, cudaEventDisableTiming);
        cudaEventCreateWithFlags(&s_evJoin, cudaEventDisableTiming);
        cudaFuncSetAttribute(gemm_kernel,
                             cudaFuncAttributeMaxDynamicSharedMemorySize, GEMM_SMEM);
    }

    // Fork: side stream builds the CSR skeleton while stream 0 runs the GEMM.
    cudaEventRecord(s_evFork, 0);
    cudaStreamWaitEvent(s_side, s_evFork, 0);

    zero_deg_kernel<<<(N + 4 + 255) / 256, 256, 0, s_side>>>(N);
    hist_kernel<<<(E + 255) / 256, 256, 0, s_side>>>(row, E);
    scan_kernel<<<1, 1024, 0, s_side>>>(N);
    cudaEventRecord(s_evJoin, s_side);

    dim3 ggrid((N + 127) / 128, 2);
    gemm_kernel<<<ggrid, 256, GEMM_SMEM>>>(x, W0, b0, W1, b1, att, N);

    // Join: scatter needs g_aneigh (GEMM) + g_cur (scan).
    cudaStreamWaitEvent(0, s_evJoin, 0);
    scatter_kernel<<<(E + 255) / 256, 256>>>(row, col, E);
    agg_kernel<<<(N * 32 + 255) / 256, 256>>>(scale0, offset0, scale1, offset1, out, N);
}